// round 6
// baseline (speedup 1.0000x reference)
#include <cuda_runtime.h>
#include <float.h>

#define NB   8
#define NSEQ 1024
#define NDIM 1024
#define NH   16
#define ND   64
#define MTOT (NB*NSEQ)      // 8192
#define ATTN_SCALE 0.03125f // DIM^-0.5 = 1/32

// Scratch (device globals: allocation-free per harness rules)
__device__ float g_Q [NB*NH*NSEQ*ND];   // [B,H,N,D]
__device__ float g_K [NB*NH*NSEQ*ND];
__device__ float g_V [NB*NH*NSEQ*ND];
__device__ float g_AO[NB*NSEQ*NDIM];    // attention out, [B,N,DIM]
__device__ int   g_mask[NB*NSEQ];       // canonical padded mask, 1 = visible

// ---------------------------------------------------------------------------
// Mask decode: auto-detect element width of the raw bool mask buffer
// (harness may widen numpy bool to int32/float32/bf16/uint8), write padded
// [B, N] int mask with position 0 forced visible (CLS).
// For 4-byte elems, (word != 0) == (value != 0), so i32/f32 confusion is
// harmless; we only need the element SIZE.
// ---------------------------------------------------------------------------
__global__ void decode_mask_kernel(const unsigned char* __restrict__ raw)
{
    const unsigned int* w = (const unsigned int*)raw;
    bool w4 = true, w2 = true;
    #pragma unroll
    for (int i = 0; i < 32; i++) {
        unsigned int v = w[i];
        if (v != 0u && v != 1u && v != 0x3F800000u) w4 = false;
        if (v != 0u && v != 0x3F803F80u && v != 0x3F800000u &&
            v != 0x00003F80u && v != 0x00010001u && v != 0x00000001u &&
            v != 0x00010000u) w2 = false;
    }
    int e = blockIdx.x * blockDim.x + threadIdx.x;
    if (e >= NB * NSEQ) return;
    int b = e / NSEQ, n = e % NSEQ;
    int val;
    if (n == 0) {
        val = 1;
    } else {
        int idx = b * (NSEQ - 1) + (n - 1);
        if (w4)      val = (((const unsigned int*)raw)[idx]   != 0u);
        else if (w2) val = (((const unsigned short*)raw)[idx] != 0);
        else         val = (raw[idx] != 0);
    }
    g_mask[e] = val;
}

// ---------------------------------------------------------------------------
// GEMM1: C[8192,3072] = X[8192,1024] @ [Wqk;Wv]^T ; epilogue adds pos to Q,K
// and scatters into [B,H,N,D].
// ---------------------------------------------------------------------------
__global__ __launch_bounds__(256) void qkv_gemm(
    const float* __restrict__ X, const float* __restrict__ Wqk,
    const float* __restrict__ Wv, const float* __restrict__ pos)
{
    __shared__ float As[16][128];
    __shared__ float Bs[16][128];
    const int K_ = NDIM;
    const int tid = threadIdx.x;
    const int tx = tid & 15, ty = tid >> 4;
    const int m0 = blockIdx.y * 128;
    const int n0 = blockIdx.x * 128;
    const float* Bbase = (n0 < 2048) ? (Wqk + (size_t)n0 * K_)
                                     : (Wv  + (size_t)(n0 - 2048) * K_);

    float acc[8][8];
    #pragma unroll
    for (int i = 0; i < 8; i++)
        #pragma unroll
        for (int j = 0; j < 8; j++) acc[i][j] = 0.f;

    for (int k0 = 0; k0 < K_; k0 += 16) {
        #pragma unroll
        for (int it = 0; it < 2; it++) {
            int v   = tid + it * 256;     // 0..511
            int row = v >> 2;             // 0..127
            int c4  = (v & 3) * 4;        // 0,4,8,12
            float4 a = *(const float4*)(X + (size_t)(m0 + row) * K_ + k0 + c4);
            As[c4+0][row] = a.x; As[c4+1][row] = a.y;
            As[c4+2][row] = a.z; As[c4+3][row] = a.w;
            float4 b = *(const float4*)(Bbase + (size_t)row * K_ + k0 + c4);
            Bs[c4+0][row] = b.x; Bs[c4+1][row] = b.y;
            Bs[c4+2][row] = b.z; Bs[c4+3][row] = b.w;
        }
        __syncthreads();
        #pragma unroll
        for (int kk = 0; kk < 16; kk++) {
            float a[8], b[8];
            #pragma unroll
            for (int i = 0; i < 8; i++) a[i] = As[kk][ty*8 + i];
            #pragma unroll
            for (int j = 0; j < 8; j++) b[j] = Bs[kk][tx*8 + j];
            #pragma unroll
            for (int i = 0; i < 8; i++)
                #pragma unroll
                for (int j = 0; j < 8; j++) acc[i][j] += a[i] * b[j];
        }
        __syncthreads();
    }

    // Epilogue: scatter to Q/K/V [B,H,N,D]; add pos for Q and K.
    #pragma unroll
    for (int i = 0; i < 8; i++) {
        int m = m0 + ty*8 + i;
        int b = m >> 10, n = m & 1023;
        #pragma unroll
        for (int j = 0; j < 8; j++) {
            int jg = n0 + tx*8 + j;
            float c = acc[i][j];
            if (jg < 2048) {
                int jj = jg & 1023;
                c += pos[(size_t)m * NDIM + jj];
                int h = jj >> 6, d = jj & 63;
                float* dst = (jg < 1024) ? g_Q : g_K;
                dst[(size_t)(b*NH + h) * (NSEQ*ND) + n*ND + d] = c;
            } else {
                int jj = jg - 2048;
                int h = jj >> 6, d = jj & 63;
                g_V[(size_t)(b*NH + h) * (NSEQ*ND) + n*ND + d] = c;
            }
        }
    }
}

// ---------------------------------------------------------------------------
// Flash attention: one CTA per (b,h, 64-row Q tile). Online softmax.
// Masked entries use -FLT_MAX (matches reference: fully masked rows become
// uniform attention).
// ---------------------------------------------------------------------------
#define SSTR 65
#define ATTN_SMEM (3 * 64 * SSTR * 4)

__global__ __launch_bounds__(256) void attn_kernel()
{
    extern __shared__ float sm[];
    float* Qs  = sm;                 // [64][SSTR]
    float* KPs = sm + 64*SSTR;       // K tile, reused as P tile
    float* Vs  = sm + 2*64*SSTR;
    __shared__ int kmask_s[64];

    const int bh = blockIdx.y;
    const int b  = bh >> 4;
    const int h  = bh & 15;
    const int q0 = blockIdx.x * 64;
    const int tid = threadIdx.x;
    const int tx = tid & 15, ty = tid >> 4;
    const int r0 = ty * 4, c0 = tx * 4;

    const float* Qp = g_Q + (size_t)bh * (NSEQ*ND);
    const float* Kp = g_K + (size_t)bh * (NSEQ*ND);
    const float* Vp = g_V + (size_t)bh * (NSEQ*ND);

    // Load Q tile (64x64): 1024 float4, 4 per thread
    #pragma unroll
    for (int it = 0; it < 4; it++) {
        int v   = tid + it * 256;
        int row = v >> 4;
        int c4  = (v & 15) * 4;
        float4 q = *(const float4*)(Qp + (size_t)(q0 + row) * ND + c4);
        Qs[row*SSTR + c4+0] = q.x; Qs[row*SSTR + c4+1] = q.y;
        Qs[row*SSTR + c4+2] = q.z; Qs[row*SSTR + c4+3] = q.w;
    }

    bool rmask[4];
    #pragma unroll
    for (int i = 0; i < 4; i++) {
        int iq = q0 + r0 + i;
        rmask[i] = (g_mask[b*NSEQ + iq] != 0);
    }

    float mrun[4], lrun[4], O[4][4];
    #pragma unroll
    for (int i = 0; i < 4; i++) {
        mrun[i] = -FLT_MAX; lrun[i] = 0.f;
        #pragma unroll
        for (int j = 0; j < 4; j++) O[i][j] = 0.f;
    }

    for (int kt = 0; kt < NSEQ/64; kt++) {
        __syncthreads();  // prev PV done (KPs reuse) + Q ready on first iter
        #pragma unroll
        for (int it = 0; it < 4; it++) {
            int v   = tid + it * 256;
            int row = v >> 4;
            int c4  = (v & 15) * 4;
            const float* ks = Kp + (size_t)(kt*64 + row) * ND + c4;
            float4 kv = *(const float4*)ks;
            KPs[row*SSTR + c4+0] = kv.x; KPs[row*SSTR + c4+1] = kv.y;
            KPs[row*SSTR + c4+2] = kv.z; KPs[row*SSTR + c4+3] = kv.w;
            float4 vv = *(const float4*)(Vp + (size_t)(kt*64 + row) * ND + c4);
            Vs[row*SSTR + c4+0] = vv.x; Vs[row*SSTR + c4+1] = vv.y;
            Vs[row*SSTR + c4+2] = vv.z; Vs[row*SSTR + c4+3] = vv.w;
        }
        if (tid < 64) {
            kmask_s[tid] = g_mask[b*NSEQ + kt*64 + tid];
        }
        __syncthreads();

        // S = Q K^T (4x4 microtile)
        float s[4][4];
        #pragma unroll
        for (int i = 0; i < 4; i++)
            #pragma unroll
            for (int j = 0; j < 4; j++) s[i][j] = 0.f;
        #pragma unroll 8
        for (int k = 0; k < 64; k++) {
            float qa[4], kb[4];
            #pragma unroll
            for (int i = 0; i < 4; i++) qa[i] = Qs[(r0+i)*SSTR + k];
            #pragma unroll
            for (int j = 0; j < 4; j++) kb[j] = KPs[(c0+j)*SSTR + k];
            #pragma unroll
            for (int i = 0; i < 4; i++)
                #pragma unroll
                for (int j = 0; j < 4; j++) s[i][j] += qa[i] * kb[j];
        }

        // scale + mask
        int km[4];
        #pragma unroll
        for (int j = 0; j < 4; j++) km[j] = kmask_s[c0 + j];
        #pragma unroll
        for (int i = 0; i < 4; i++)
            #pragma unroll
            for (int j = 0; j < 4; j++)
                s[i][j] = (rmask[i] && km[j]) ? s[i][j] * ATTN_SCALE : -FLT_MAX;

        // row max across the 16-lane halfwarp
        float tmax[4];
        #pragma unroll
        for (int i = 0; i < 4; i++) {
            tmax[i] = fmaxf(fmaxf(s[i][0], s[i][1]), fmaxf(s[i][2], s[i][3]));
        }
        #pragma unroll
        for (int off = 8; off >= 1; off >>= 1)
            #pragma unroll
            for (int i = 0; i < 4; i++)
                tmax[i] = fmaxf(tmax[i], __shfl_xor_sync(0xffffffffu, tmax[i], off));

        float mnew[4], alpha[4], p[4][4], lsum[4];
        #pragma unroll
        for (int i = 0; i < 4; i++) {
            mnew[i]  = fmaxf(mrun[i], tmax[i]);
            alpha[i] = __expf(mrun[i] - mnew[i]);
            lsum[i]  = 0.f;
            #pragma unroll
            for (int j = 0; j < 4; j++) {
                p[i][j] = __expf(s[i][j] - mnew[i]);
                lsum[i] += p[i][j];
            }
        }
        #pragma unroll
        for (int off = 8; off >= 1; off >>= 1)
            #pragma unroll
            for (int i = 0; i < 4; i++)
                lsum[i] += __shfl_xor_sync(0xffffffffu, lsum[i], off);
        #pragma unroll
        for (int i = 0; i < 4; i++) {
            lrun[i] = lrun[i] * alpha[i] + lsum[i];
            mrun[i] = mnew[i];
            #pragma unroll
            for (int j = 0; j < 4; j++) O[i][j] *= alpha[i];
        }

        __syncthreads();  // all K reads done before overwriting KPs with P
        #pragma unroll
        for (int i = 0; i < 4; i++)
            #pragma unroll
            for (int j = 0; j < 4; j++)
                KPs[(r0+i)*SSTR + (c0+j)] = p[i][j];
        __syncthreads();

        // O += P @ V
        #pragma unroll 8
        for (int k = 0; k < 64; k++) {
            float pa[4], vb[4];
            #pragma unroll
            for (int i = 0; i < 4; i++) pa[i] = KPs[(r0+i)*SSTR + k];
            #pragma unroll
            for (int j = 0; j < 4; j++) vb[j] = Vs[k*SSTR + c0 + j];
            #pragma unroll
            for (int i = 0; i < 4; i++)
                #pragma unroll
                for (int j = 0; j < 4; j++) O[i][j] += pa[i] * vb[j];
        }
    }

    // normalize & store to [B,N,DIM]
    #pragma unroll
    for (int i = 0; i < 4; i++) {
        float inv = 1.0f / lrun[i];
        int iq = q0 + r0 + i;
        float4 o4 = make_float4(O[i][0]*inv, O[i][1]*inv, O[i][2]*inv, O[i][3]*inv);
        *(float4*)(g_AO + (size_t)(b*NSEQ + iq) * NDIM + h*ND + c0) = o4;
    }
}

// ---------------------------------------------------------------------------
// GEMM3: out[8192,1024] = AO @ Wout^T + bout
// ---------------------------------------------------------------------------
__global__ __launch_bounds__(256) void out_gemm(
    const float* __restrict__ Wout, const float* __restrict__ bout,
    float* __restrict__ out)
{
    __shared__ float As[16][128];
    __shared__ float Bs[16][128];
    const int K_ = NDIM;
    const int tid = threadIdx.x;
    const int tx = tid & 15, ty = tid >> 4;
    const int m0 = blockIdx.y * 128;
    const int n0 = blockIdx.x * 128;

    float acc[8][8];
    #pragma unroll
    for (int i = 0; i < 8; i++)
        #pragma unroll
        for (int j = 0; j < 8; j++) acc[i][j] = 0.f;

    for (int k0 = 0; k0 < K_; k0 += 16) {
        #pragma unroll
        for (int it = 0; it < 2; it++) {
            int v   = tid + it * 256;
            int row = v >> 2;
            int c4  = (v & 3) * 4;
            float4 a = *(const float4*)(g_AO + (size_t)(m0 + row) * K_ + k0 + c4);
            As[c4+0][row] = a.x; As[c4+1][row] = a.y;
            As[c4+2][row] = a.z; As[c4+3][row] = a.w;
            float4 b = *(const float4*)(Wout + (size_t)(n0 + row) * K_ + k0 + c4);
            Bs[c4+0][row] = b.x; Bs[c4+1][row] = b.y;
            Bs[c4+2][row] = b.z; Bs[c4+3][row] = b.w;
        }
        __syncthreads();
        #pragma unroll
        for (int kk = 0; kk < 16; kk++) {
            float a[8], b[8];
            #pragma unroll
            for (int i = 0; i < 8; i++) a[i] = As[kk][ty*8 + i];
            #pragma unroll
            for (int j = 0; j < 8; j++) b[j] = Bs[kk][tx*8 + j];
            #pragma unroll
            for (int i = 0; i < 8; i++)
                #pragma unroll
                for (int j = 0; j < 8; j++) acc[i][j] += a[i] * b[j];
        }
        __syncthreads();
    }

    #pragma unroll
    for (int i = 0; i < 8; i++) {
        int m = m0 + ty*8 + i;
        #pragma unroll
        for (int j = 0; j < 8; j++) {
            int jg = n0 + tx*8 + j;
            out[(size_t)m * NDIM + jg] = acc[i][j] + bout[jg];
        }
    }
}

// ---------------------------------------------------------------------------
extern "C" void kernel_launch(void* const* d_in, const int* in_sizes, int n_in,
                              void* d_out, int out_size)
{
    const float*         x    = (const float*)d_in[0];
    const unsigned char* mask = (const unsigned char*)d_in[1];
    const float*         pos  = (const float*)d_in[2];
    const float*         Wqk  = (const float*)d_in[3];
    const float*         Wv   = (const float*)d_in[4];
    const float*         Wout = (const float*)d_in[5];
    const float*         bout = (const float*)d_in[6];
    float*               out  = (float*)d_out;

    cudaFuncSetAttribute(attn_kernel,
                         cudaFuncAttributeMaxDynamicSharedMemorySize, ATTN_SMEM);

    decode_mask_kernel<<<(NB*NSEQ + 255) / 256, 256>>>(mask);
    qkv_gemm<<<dim3(3072/128, MTOT/128), 256>>>(x, Wqk, Wv, pos);
    attn_kernel<<<dim3(NSEQ/64, NB*NH), 256, ATTN_SMEM>>>();
    out_gemm<<<dim3(NDIM/128, MTOT/128), 256>>>(Wout, bout, out);
}

// round 10
// speedup vs baseline: 1.6992x; 1.6992x over previous
#include <cuda_runtime.h>
#include <cuda_bf16.h>
#include <float.h>
#include <stdint.h>

#define NB   8
#define NSEQ 1024
#define NDIM 1024
#define NH   16
#define ND   64
#define MTOT (NB*NSEQ)      // 8192
#define KSP  3072           // split-K: [hi|hi|lo] x 1024
#define ATTN_SCALE 0.03125f

// ---------------- device scratch (allocation-free) ----------------
__device__ float g_Q [NB*NH*NSEQ*ND];
__device__ float g_K [NB*NH*NSEQ*ND];
__device__ float g_V [NB*NH*NSEQ*ND];
__device__ int   g_mask[NB*NSEQ];
__device__ __nv_bfloat16 g_Xbig  [(size_t)MTOT*KSP];   // [8192,3072] = [hi|hi|lo]
__device__ __nv_bfloat16 g_Wbig  [(size_t)3072*KSP];   // rows: 2048 Wqk + 1024 Wv, [hi|lo|hi]
__device__ __nv_bfloat16 g_AObig [(size_t)MTOT*KSP];
__device__ __nv_bfloat16 g_WoutBig[(size_t)1024*KSP];

// ---------------- helpers ----------------
__device__ __forceinline__ uint32_t smem_u32(const void* p) {
    uint32_t a;
    asm("{ .reg .u64 t; cvta.to.shared.u64 t, %1; cvt.u32.u64 %0, t; }"
        : "=r"(a) : "l"(p));
    return a;
}
#define SW128(o) ((o) ^ (((o) >> 3) & 0x70))

__device__ __forceinline__ void cp_async16(uint32_t dst, const void* src) {
    asm volatile("cp.async.cg.shared.global [%0], [%1], 16;"
                 :: "r"(dst), "l"(src) : "memory");
}
#define CP_COMMIT() asm volatile("cp.async.commit_group;" ::: "memory")
#define CP_WAIT(n)  asm volatile("cp.async.wait_group %0;" :: "n"(n) : "memory")

__device__ __forceinline__ void ldsm_x4(uint32_t a, uint32_t& r0, uint32_t& r1,
                                        uint32_t& r2, uint32_t& r3) {
    asm volatile("ldmatrix.sync.aligned.m8n8.x4.shared.b16 {%0,%1,%2,%3}, [%4];"
                 : "=r"(r0), "=r"(r1), "=r"(r2), "=r"(r3) : "r"(a));
}
__device__ __forceinline__ void mma16816(float* c, const uint32_t* a,
                                         uint32_t b0, uint32_t b1) {
    asm volatile(
        "mma.sync.aligned.m16n8k16.row.col.f32.bf16.bf16.f32 "
        "{%0,%1,%2,%3}, {%4,%5,%6,%7}, {%8,%9}, {%0,%1,%2,%3};"
        : "+f"(c[0]), "+f"(c[1]), "+f"(c[2]), "+f"(c[3])
        : "r"(a[0]), "r"(a[1]), "r"(a[2]), "r"(a[3]), "r"(b0), "r"(b1));
}

// ---------------------------------------------------------------------------
// Mask decode (element-width autodetect, CLS forced visible)
// ---------------------------------------------------------------------------
__global__ void decode_mask_kernel(const unsigned char* __restrict__ raw)
{
    const unsigned int* w = (const unsigned int*)raw;
    bool w4 = true, w2 = true;
    #pragma unroll
    for (int i = 0; i < 32; i++) {
        unsigned int v = w[i];
        if (v != 0u && v != 1u && v != 0x3F800000u) w4 = false;
        if (v != 0u && v != 0x3F803F80u && v != 0x3F800000u &&
            v != 0x00003F80u && v != 0x00010001u && v != 0x00000001u &&
            v != 0x00010000u) w2 = false;
    }
    int e = blockIdx.x * blockDim.x + threadIdx.x;
    if (e >= NB * NSEQ) return;
    int b = e / NSEQ, n = e % NSEQ;
    int val;
    if (n == 0) val = 1;
    else {
        int idx = b * (NSEQ - 1) + (n - 1);
        if (w4)      val = (((const unsigned int*)raw)[idx]   != 0u);
        else if (w2) val = (((const unsigned short*)raw)[idx] != 0);
        else         val = (raw[idx] != 0);
    }
    g_mask[e] = val;
}

// ---------------------------------------------------------------------------
// Split fp32 [rows,1024] -> bf16 [rows,3072].
// A-side (dsel 0): [hi | hi | lo] ; B-side (dsel 1,2): [hi | lo | hi]
// so the K=3072 dot product = hi*hi + hi*lo + lo*hi.
// ---------------------------------------------------------------------------
__global__ void split3(const float* __restrict__ src, int dsel, int rowoff, int nelem)
{
    int i = blockIdx.x * blockDim.x + threadIdx.x;
    if (i >= nelem) return;
    __nv_bfloat16* dst = (dsel == 0) ? g_Xbig : (dsel == 1) ? g_Wbig : g_WoutBig;
    int r = i >> 10, k = i & 1023;
    float x = src[i];
    __nv_bfloat16 h = __float2bfloat16(x);
    float rem = x - __bfloat162float(h);
    __nv_bfloat16 l = __float2bfloat16(rem);
    size_t base = (size_t)(rowoff + r) * KSP;
    if (dsel == 0) {            // A-side: [hi|hi|lo]
        dst[base + k]        = h;
        dst[base + 1024 + k] = h;
        dst[base + 2048 + k] = l;
    } else {                    // B-side: [hi|lo|hi]
        dst[base + k]        = h;
        dst[base + 1024 + k] = l;
        dst[base + 2048 + k] = h;
    }
}

// ---------------------------------------------------------------------------
// bf16 HMMA GEMM: C[M,N] = A[M,3072] @ B[N,3072]^T, fp32 accum.
// CTA tile 128x128, BK=64, 8 warps (2x4), warp tile 64x32, cp.async 2-stage.
// EPI=0: qkv scatter (+pos). EPI=1: out = C + bias.
// ---------------------------------------------------------------------------
#define BM 128
#define BN 128
#define BK 64
#define NKB (KSP/BK)            // 48
#define TILE_B (BM*BK*2)        // 16384 bytes per operand tile
#define GEMM_SMEM (4*TILE_B + 1024)

template<int EPI>
__global__ __launch_bounds__(256, 2) void hmma_gemm(
    const float* __restrict__ pos, const float* __restrict__ bout,
    float* __restrict__ out)
{
    extern __shared__ char dsm[];
    const __nv_bfloat16* __restrict__ Ab = (EPI == 0) ? g_Xbig : g_AObig;
    const __nv_bfloat16* __restrict__ Bb = (EPI == 0) ? g_Wbig : g_WoutBig;

    const int tid  = threadIdx.x;
    const int lane = tid & 31;
    const int wid  = tid >> 5;
    const int wm   = wid >> 2;          // 0..1
    const int wn   = wid & 3;           // 0..3
    const int m0 = blockIdx.y * BM;
    const int n0 = blockIdx.x * BN;

    uint32_t raw = smem_u32(dsm);
    uint32_t tb  = (raw + 1023u) & ~1023u;
    const uint32_t sA[2] = { tb,              tb + 2*TILE_B };
    const uint32_t sB[2] = { tb + TILE_B,     tb + 3*TILE_B };

    // cp.async tile loader: 2048 x 16B chunks per (A,B) stage, 8 per thread
    auto load_stage = [&](int kb, int s) {
        const __nv_bfloat16* ag = Ab + (size_t)m0 * KSP + kb * BK;
        const __nv_bfloat16* bg = Bb + (size_t)n0 * KSP + kb * BK;
        #pragma unroll
        for (int it = 0; it < 4; it++) {
            int v = tid + it * 256;         // 0..1023
            int r = v >> 3, c16 = (v & 7) * 16;
            uint32_t off = SW128((uint32_t)(r * 128 + c16));
            cp_async16(sA[s] + off, (const char*)(ag + (size_t)r * KSP) + c16);
            cp_async16(sB[s] + off, (const char*)(bg + (size_t)r * KSP) + c16);
        }
        CP_COMMIT();
    };

    float acc[4][4][4];
    #pragma unroll
    for (int mi = 0; mi < 4; mi++)
        #pragma unroll
        for (int ni = 0; ni < 4; ni++)
            #pragma unroll
            for (int r = 0; r < 4; r++) acc[mi][ni][r] = 0.f;

    load_stage(0, 0);

    for (int kb = 0; kb < NKB; kb++) {
        const int s = kb & 1;
        if (kb + 1 < NKB) load_stage(kb + 1, (kb + 1) & 1);
        if (kb + 1 < NKB) { CP_WAIT(1); } else { CP_WAIT(0); }
        __syncthreads();

        #pragma unroll
        for (int ks = 0; ks < 4; ks++) {
            const uint32_t bytecol = ks * 32 + ((lane >> 4) * 16);
            uint32_t af[4][4];
            #pragma unroll
            for (int mi = 0; mi < 4; mi++) {
                uint32_t row = wm * 64 + mi * 16 + (lane & 15);
                uint32_t a = sA[s] + SW128(row * 128 + bytecol);
                ldsm_x4(a, af[mi][0], af[mi][1], af[mi][2], af[mi][3]);
            }
            uint32_t bf[2][4];
            #pragma unroll
            for (int nj = 0; nj < 2; nj++) {
                uint32_t nrow = wn * 32 + nj * 16 + (lane & 15);
                uint32_t a = sB[s] + SW128(nrow * 128 + bytecol);
                ldsm_x4(a, bf[nj][0], bf[nj][1], bf[nj][2], bf[nj][3]);
            }
            #pragma unroll
            for (int mi = 0; mi < 4; mi++)
                #pragma unroll
                for (int ni = 0; ni < 4; ni++) {
                    int nj = ni >> 1, hh = ni & 1;
                    mma16816(acc[mi][ni], af[mi], bf[nj][hh], bf[nj][hh + 2]);
                }
        }
        __syncthreads();
    }

    // ---------------- epilogue ----------------
    const int qrow = lane >> 2;
    const int qcol = (lane & 3) * 2;
    #pragma unroll
    for (int ni = 0; ni < 4; ni++) {
        const int jg = n0 + wn * 32 + ni * 8 + qcol;
        #pragma unroll
        for (int mi = 0; mi < 4; mi++) {
            #pragma unroll
            for (int half = 0; half < 2; half++) {
                const int m = m0 + wm * 64 + mi * 16 + qrow + half * 8;
                float v0 = acc[mi][ni][half * 2 + 0];
                float v1 = acc[mi][ni][half * 2 + 1];
                if (EPI == 0) {
                    const int b = m >> 10, n = m & 1023;
                    float* dst; int jj; bool addpos;
                    if (jg < 1024)      { jj = jg;        dst = g_Q; addpos = true;  }
                    else if (jg < 2048) { jj = jg - 1024; dst = g_K; addpos = true;  }
                    else                { jj = jg - 2048; dst = g_V; addpos = false; }
                    if (addpos) {
                        float2 pv = *(const float2*)(pos + (size_t)m * NDIM + jj);
                        v0 += pv.x; v1 += pv.y;
                    }
                    const int h = jj >> 6, d0 = jj & 63;
                    *(float2*)(dst + ((size_t)(b * NH + h) * NSEQ + n) * ND + d0)
                        = make_float2(v0, v1);
                } else {
                    float2 bv = *(const float2*)(bout + jg);
                    *(float2*)(out + (size_t)m * NDIM + jg)
                        = make_float2(v0 + bv.x, v1 + bv.y);
                }
            }
        }
    }
}

// ---------------------------------------------------------------------------
// Flash attention (fp32 SIMT); epilogue writes bf16 split AO ([hi|hi|lo]).
// ---------------------------------------------------------------------------
#define SSTR 65
#define ATTN_SMEM (3 * 64 * SSTR * 4)

__global__ __launch_bounds__(256) void attn_kernel()
{
    extern __shared__ float sm[];
    float* Qs  = sm;
    float* KPs = sm + 64*SSTR;
    float* Vs  = sm + 2*64*SSTR;
    __shared__ int kmask_s[64];

    const int bh = blockIdx.y;
    const int b  = bh >> 4;
    const int h  = bh & 15;
    const int q0 = blockIdx.x * 64;
    const int tid = threadIdx.x;
    const int tx = tid & 15, ty = tid >> 4;
    const int r0 = ty * 4, c0 = tx * 4;

    const float* Qp = g_Q + (size_t)bh * (NSEQ*ND);
    const float* Kp = g_K + (size_t)bh * (NSEQ*ND);
    const float* Vp = g_V + (size_t)bh * (NSEQ*ND);

    #pragma unroll
    for (int it = 0; it < 4; it++) {
        int v   = tid + it * 256;
        int row = v >> 4;
        int c4  = (v & 15) * 4;
        float4 q = *(const float4*)(Qp + (size_t)(q0 + row) * ND + c4);
        Qs[row*SSTR + c4+0] = q.x; Qs[row*SSTR + c4+1] = q.y;
        Qs[row*SSTR + c4+2] = q.z; Qs[row*SSTR + c4+3] = q.w;
    }

    bool rmask[4];
    #pragma unroll
    for (int i = 0; i < 4; i++)
        rmask[i] = (g_mask[b*NSEQ + q0 + r0 + i] != 0);

    float mrun[4], lrun[4], O[4][4];
    #pragma unroll
    for (int i = 0; i < 4; i++) {
        mrun[i] = -FLT_MAX; lrun[i] = 0.f;
        #pragma unroll
        for (int j = 0; j < 4; j++) O[i][j] = 0.f;
    }

    for (int kt = 0; kt < NSEQ/64; kt++) {
        __syncthreads();
        #pragma unroll
        for (int it = 0; it < 4; it++) {
            int v   = tid + it * 256;
            int row = v >> 4;
            int c4  = (v & 15) * 4;
            float4 kv = *(const float4*)(Kp + (size_t)(kt*64 + row) * ND + c4);
            KPs[row*SSTR + c4+0] = kv.x; KPs[row*SSTR + c4+1] = kv.y;
            KPs[row*SSTR + c4+2] = kv.z; KPs[row*SSTR + c4+3] = kv.w;
            float4 vv = *(const float4*)(Vp + (size_t)(kt*64 + row) * ND + c4);
            Vs[row*SSTR + c4+0] = vv.x; Vs[row*SSTR + c4+1] = vv.y;
            Vs[row*SSTR + c4+2] = vv.z; Vs[row*SSTR + c4+3] = vv.w;
        }
        if (tid < 64) kmask_s[tid] = g_mask[b*NSEQ + kt*64 + tid];
        __syncthreads();

        float s[4][4];
        #pragma unroll
        for (int i = 0; i < 4; i++)
            #pragma unroll
            for (int j = 0; j < 4; j++) s[i][j] = 0.f;
        #pragma unroll 8
        for (int k = 0; k < 64; k++) {
            float qa[4], kb[4];
            #pragma unroll
            for (int i = 0; i < 4; i++) qa[i] = Qs[(r0+i)*SSTR + k];
            #pragma unroll
            for (int j = 0; j < 4; j++) kb[j] = KPs[(c0+j)*SSTR + k];
            #pragma unroll
            for (int i = 0; i < 4; i++)
                #pragma unroll
                for (int j = 0; j < 4; j++) s[i][j] += qa[i] * kb[j];
        }

        int km[4];
        #pragma unroll
        for (int j = 0; j < 4; j++) km[j] = kmask_s[c0 + j];
        #pragma unroll
        for (int i = 0; i < 4; i++)
            #pragma unroll
            for (int j = 0; j < 4; j++)
                s[i][j] = (rmask[i] && km[j]) ? s[i][j] * ATTN_SCALE : -FLT_MAX;

        float tmax[4];
        #pragma unroll
        for (int i = 0; i < 4; i++)
            tmax[i] = fmaxf(fmaxf(s[i][0], s[i][1]), fmaxf(s[i][2], s[i][3]));
        #pragma unroll
        for (int off = 8; off >= 1; off >>= 1)
            #pragma unroll
            for (int i = 0; i < 4; i++)
                tmax[i] = fmaxf(tmax[i], __shfl_xor_sync(0xffffffffu, tmax[i], off));

        float mnew[4], alpha[4], p[4][4], lsum[4];
        #pragma unroll
        for (int i = 0; i < 4; i++) {
            mnew[i]  = fmaxf(mrun[i], tmax[i]);
            alpha[i] = __expf(mrun[i] - mnew[i]);
            lsum[i]  = 0.f;
            #pragma unroll
            for (int j = 0; j < 4; j++) {
                p[i][j] = __expf(s[i][j] - mnew[i]);
                lsum[i] += p[i][j];
            }
        }
        #pragma unroll
        for (int off = 8; off >= 1; off >>= 1)
            #pragma unroll
            for (int i = 0; i < 4; i++)
                lsum[i] += __shfl_xor_sync(0xffffffffu, lsum[i], off);
        #pragma unroll
        for (int i = 0; i < 4; i++) {
            lrun[i] = lrun[i] * alpha[i] + lsum[i];
            mrun[i] = mnew[i];
            #pragma unroll
            for (int j = 0; j < 4; j++) O[i][j] *= alpha[i];
        }

        __syncthreads();
        #pragma unroll
        for (int i = 0; i < 4; i++)
            #pragma unroll
            for (int j = 0; j < 4; j++)
                KPs[(r0+i)*SSTR + (c0+j)] = p[i][j];
        __syncthreads();

        #pragma unroll 8
        for (int k = 0; k < 64; k++) {
            float pa[4], vb[4];
            #pragma unroll
            for (int i = 0; i < 4; i++) pa[i] = KPs[(r0+i)*SSTR + k];
            #pragma unroll
            for (int j = 0; j < 4; j++) vb[j] = Vs[k*SSTR + c0 + j];
            #pragma unroll
            for (int i = 0; i < 4; i++)
                #pragma unroll
                for (int j = 0; j < 4; j++) O[i][j] += pa[i] * vb[j];
        }
    }

    // epilogue: normalize, split to bf16 [hi|hi|lo], write AObig[token, 3072]
    #pragma unroll
    for (int i = 0; i < 4; i++) {
        float inv = 1.0f / lrun[i];
        int iq = q0 + r0 + i;
        float f0 = O[i][0]*inv, f1 = O[i][1]*inv, f2 = O[i][2]*inv, f3 = O[i][3]*inv;
        __nv_bfloat162 h01 = __float22bfloat162_rn(make_float2(f0, f1));
        __nv_bfloat162 h23 = __float22bfloat162_rn(make_float2(f2, f3));
        float r0f = f0 - __bfloat162float(h01.x);
        float r1f = f1 - __bfloat162float(h01.y);
        float r2f = f2 - __bfloat162float(h23.x);
        float r3f = f3 - __bfloat162float(h23.y);
        __nv_bfloat162 l01 = __float22bfloat162_rn(make_float2(r0f, r1f));
        __nv_bfloat162 l23 = __float22bfloat162_rn(make_float2(r2f, r3f));
        size_t base = (size_t)(b*NSEQ + iq) * KSP + h*ND + c0;
        __nv_bfloat162* p0 = (__nv_bfloat162*)(g_AObig + base);
        __nv_bfloat162* p1 = (__nv_bfloat162*)(g_AObig + base + 1024);
        __nv_bfloat162* p2 = (__nv_bfloat162*)(g_AObig + base + 2048);
        p0[0] = h01; p0[1] = h23;
        p1[0] = h01; p1[1] = h23;
        p2[0] = l01; p2[1] = l23;
    }
}

// ---------------------------------------------------------------------------
extern "C" void kernel_launch(void* const* d_in, const int* in_sizes, int n_in,
                              void* d_out, int out_size)
{
    const float*         x    = (const float*)d_in[0];
    const unsigned char* mask = (const unsigned char*)d_in[1];
    const float*         pos  = (const float*)d_in[2];
    const float*         Wqk  = (const float*)d_in[3];
    const float*         Wv   = (const float*)d_in[4];
    const float*         Wout = (const float*)d_in[5];
    const float*         bout = (const float*)d_in[6];
    float*               out  = (float*)d_out;

    cudaFuncSetAttribute(attn_kernel,
                         cudaFuncAttributeMaxDynamicSharedMemorySize, ATTN_SMEM);
    cudaFuncSetAttribute(hmma_gemm<0>,
                         cudaFuncAttributeMaxDynamicSharedMemorySize, GEMM_SMEM);
    cudaFuncSetAttribute(hmma_gemm<1>,
                         cudaFuncAttributeMaxDynamicSharedMemorySize, GEMM_SMEM);

    decode_mask_kernel<<<(NB*NSEQ + 255) / 256, 256>>>(mask);
    split3<<<(MTOT*1024 + 255) / 256, 256>>>(x,    0, 0,    MTOT*1024);
    split3<<<(2048*1024 + 255) / 256, 256>>>(Wqk,  1, 0,    2048*1024);
    split3<<<(1024*1024 + 255) / 256, 256>>>(Wv,   1, 2048, 1024*1024);
    split3<<<(1024*1024 + 255) / 256, 256>>>(Wout, 2, 0,    1024*1024);

    hmma_gemm<0><<<dim3(KSP/BN, MTOT/BM), 256, GEMM_SMEM>>>(pos, nullptr, nullptr);
    attn_kernel<<<dim3(NSEQ/64, NB*NH), 256, ATTN_SMEM>>>();
    hmma_gemm<1><<<dim3(NDIM/BN, MTOT/BM), 256, GEMM_SMEM>>>(nullptr, bout, out);
}